// round 14
// baseline (speedup 1.0000x reference)
#include <cuda_runtime.h>
#include <cuda_bf16.h>
#include <cstdint>

#define Bn 1024
#define Hn 256
#define Gn 768
#define On 512
#define Tn 60
#define Cc 15
#define MAXG 18
#define OT (On*Tn)
#define MAXU 10

__device__ __align__(16) uint4 g_Bw[120 * 6144];
__device__ __align__(16) uint4 g_Bo[120 * 4096];
__device__ __align__(16) uint4 g_Bx[120 * 6144];
__device__ __align__(16) uint32_t g_h[2 * MAXG * 2 * 16384];
__device__ int g_perm[Bn], g_gcam[MAXG], g_goff[MAXG], g_gcnt[MAXG], g_ngrp, g_bar[MAXG];

__device__ __forceinline__ float sigf(float v) { return 1.f / (1.f + __expf(-v)); }
__device__ __forceinline__ float tanhf_(float v) { return 2.f * sigf(2.f * v) - 1.f; }
__device__ __forceinline__ void bfsplit2(float f0, float f1, uint32_t& hi, uint32_t& lo) {
    unsigned short a = __bfloat16_as_ushort(__float2bfloat16_rn(f0));
    unsigned short b = __bfloat16_as_ushort(__float2bfloat16_rn(f1));
    float r0 = f0 - __uint_as_float((uint32_t)a << 16);
    float r1 = f1 - __uint_as_float((uint32_t)b << 16);
    unsigned short c = __bfloat16_as_ushort(__float2bfloat16_rn(r0));
    unsigned short d = __bfloat16_as_ushort(__float2bfloat16_rn(r1));
    hi = (uint32_t)a | ((uint32_t)b << 16);
    lo = (uint32_t)c | ((uint32_t)d << 16);
}
__device__ __forceinline__ void mma4(float* c, const uint32_t* a, uint32_t b0, uint32_t b1) {
    asm volatile("mma.sync.aligned.m16n8k16.row.col.f32.bf16.bf16.f32 "
                 "{%0,%1,%2,%3},{%4,%5,%6,%7},{%8,%9},{%0,%1,%2,%3};"
                 : "+f"(c[0]), "+f"(c[1]), "+f"(c[2]), "+f"(c[3])
                 : "r"(a[0]), "r"(a[1]), "r"(a[2]), "r"(a[3]), "r"(b0), "r"(b1));
}
__device__ __forceinline__ void ldfrag(const uint32_t* hb, int w0, int r0, int r1,
                                       uint32_t* ah, uint32_t* al) {
    ah[0] = hb[r0 * 128 + w0];             ah[1] = hb[r1 * 128 + w0];
    ah[2] = hb[r0 * 128 + w0 + 4];         ah[3] = hb[r1 * 128 + w0 + 4];
    al[0] = hb[16384 + r0 * 128 + w0];     al[1] = hb[16384 + r1 * 128 + w0];
    al[2] = hb[16384 + r0 * 128 + w0 + 4]; al[3] = hb[16384 + r1 * 128 + w0 + 4];
}

// ---------------------------------------------------------------------------
__global__ void prep(const int* __restrict__ cam, const float* __restrict__ Wi,
                     const float* __restrict__ Wh, const float* __restrict__ Wc) {
    if (blockIdx.x == 0) {
        __shared__ int cn[Cc], cu[Cc], co[Cc];
        int tid = threadIdx.x;
        if (tid < Cc) cn[tid] = 0;
        if (tid < MAXG) g_bar[tid] = 0;
        __syncthreads();
        for (int b = tid; b < Bn; b += blockDim.x) atomicAdd(&cn[cam[b]], 1);
        __syncthreads();
        if (tid == 0) {
            int o = 0;
            for (int c = 0; c < Cc; c++) { co[c] = o; cu[c] = o; o += cn[c]; }
            int g = 0;
            for (int c = 0; c < Cc; c++)
                for (int s = 0; s < cn[c] && g < MAXG; s += 128) {
                    g_gcam[g] = c; g_goff[g] = co[c] + s; g_gcnt[g] = min(128, cn[c] - s); g++;
                }
            g_ngrp = g;
        }
        __syncthreads();
        for (int b = tid; b < Bn; b += blockDim.x) { int p = atomicAdd(&cu[cam[b]], 1); g_perm[p] = b; }
    }
    int idx = blockIdx.x * blockDim.x + threadIdx.x, st = gridDim.x * blockDim.x;
    const int NWG = 120 * 12 * 512;
    for (int i = idx; i < NWG; i += st) {
        int lane = i & 31, kc = (i >> 5) & 15, T = (i >> 9) % 12, tile = i / (512 * 12);
        int c = tile >> 3, j = tile & 7;
        size_t row = (size_t)c * Gn + (T >> 2) * 256 + 32 * j + 8 * (T & 3) + (lane >> 2);
        int k0 = 16 * kc + (lane & 3) * 2;
        size_t o = (size_t)tile * 6144 + (T * 16 + kc) * 32 + lane;
        uint32_t h0, l0, h1, l1;
        const float* w = Wh + row * Hn;
        bfsplit2(w[k0], w[k0 + 1], h0, l0); bfsplit2(w[k0 + 8], w[k0 + 9], h1, l1);
        g_Bw[o] = make_uint4(h0, h1, l0, l1);
        w = Wi + row * Hn;
        bfsplit2(w[k0], w[k0 + 1], h0, l0); bfsplit2(w[k0 + 8], w[k0 + 9], h1, l1);
        g_Bx[o] = make_uint4(h0, h1, l0, l1);
    }
    const int NWO = 120 * 8 * 512;
    for (int i = idx; i < NWO; i += st) {
        int lane = i & 31, kc = (i >> 5) & 15, T = (i >> 9) & 7, tile = i / (512 * 8);
        int c = tile >> 3, j = tile & 7;
        const float* w = Wc + ((size_t)c * On + 64 * j + 8 * T + (lane >> 2)) * Hn;
        int k0 = 16 * kc + (lane & 3) * 2;
        uint32_t h0, l0, h1, l1;
        bfsplit2(w[k0], w[k0 + 1], h0, l0); bfsplit2(w[k0 + 8], w[k0 + 9], h1, l1);
        g_Bo[(size_t)tile * 4096 + (T * 16 + kc) * 32 + lane] = make_uint4(h0, h1, l0, l1);
    }
}

// ---------------------------------------------------------------------------
// 144 CTAs x 512 threads (16 warps). Each step, na*20 (mtile,Ttile) units are
// split evenly over all 16 warps (balanced per-SMSP HMMA load). Out units do
// local epilogue+STG; gate units stage D in smem; warps 0-7 do gate epilogue.
// ---------------------------------------------------------------------------
__global__ void __launch_bounds__(512, 1)
gru(const float* __restrict__ x, const float* __restrict__ b_ih,
    const float* __restrict__ b_hh, const float* __restrict__ bc,
    float* __restrict__ out) {
    extern __shared__ __align__(16) uint4 sm4[];
    uint4* sB  = sm4;                        // 6144 uint4 (gate)
    uint4* sBo = sm4 + 6144;                 // 4096 uint4 (out)
    float* dbuf = (float*)(sm4 + 10240);     // 96*128 floats (gate D staging)
    float* bcs = dbuf + 12288;               // 64
    float* bhs = bcs + 64;                   // 32
    int* samp  = (int*)(bhs + 32);           // 128

    const int grp = blockIdx.x >> 3, j = blockIdx.x & 7;
    if (grp >= g_ngrp) return;
    const int cam = g_gcam[grp], off = g_goff[grp], cnt = g_gcnt[grp];
    const int tile = cam * 8 + j;
    const int tid = threadIdx.x, wid = tid >> 5, lane = tid & 31;
    const int qr = lane >> 2, qc = lane & 3;
    const int na = (cnt + 15) >> 4;

    if (tid < 128) samp[tid] = (tid < cnt) ? g_perm[off + tid] : 0;
    if (tid < 64) bcs[tid] = bc[cam * On + 64 * j + tid];
    if (tid < 32) bhs[tid] = b_hh[cam * Gn + 512 + 32 * j + tid];
    {
        const uint4* s = g_Bw + (size_t)tile * 6144;
        for (int i = tid; i < 6144; i += 512) sB[i] = s[i];
        const uint4* s2 = g_Bo + (size_t)tile * 4096;
        for (int i = tid; i < 4096; i += 512) sBo[i] = s2[i];
    }
    __syncthreads();

    const bool epiAct = (wid < 8) && (wid < na);
    float gi[48], hold[16];
    if (epiAct) {  // gi = x@Wi + biases (warp wid owns m-tile wid)
#pragma unroll
        for (int q = 0; q < 48; q++) gi[q] = 0.f;
        const int r0 = 16 * wid + qr, r1 = r0 + 8;
        const uint4* bx = g_Bx + (size_t)tile * 6144;
        const float* x0 = (r0 < cnt) ? x + (size_t)samp[r0] * Hn : 0;
        const float* x1 = (r1 < cnt) ? x + (size_t)samp[r1] * Hn : 0;
        for (int kc = 0; kc < 16; kc++) {
            int k0 = 16 * kc + qc * 2;
            float2 p00 = x0 ? *(const float2*)(x0 + k0) : make_float2(0.f, 0.f);
            float2 p02 = x0 ? *(const float2*)(x0 + k0 + 8) : make_float2(0.f, 0.f);
            float2 p10 = x1 ? *(const float2*)(x1 + k0) : make_float2(0.f, 0.f);
            float2 p12 = x1 ? *(const float2*)(x1 + k0 + 8) : make_float2(0.f, 0.f);
            uint32_t ah[4], al[4];
            bfsplit2(p00.x, p00.y, ah[0], al[0]);
            bfsplit2(p10.x, p10.y, ah[1], al[1]);
            bfsplit2(p02.x, p02.y, ah[2], al[2]);
            bfsplit2(p12.x, p12.y, ah[3], al[3]);
            uint4 bg[12];
#pragma unroll
            for (int T = 0; T < 12; T++) bg[T] = bx[(T * 16 + kc) * 32 + lane];
#pragma unroll
            for (int T = 0; T < 12; T++) mma4(gi + 4 * T, ah, bg[T].x, bg[T].y);
#pragma unroll
            for (int T = 0; T < 12; T++) mma4(gi + 4 * T, ah, bg[T].z, bg[T].w);
#pragma unroll
            for (int T = 0; T < 12; T++) mma4(gi + 4 * T, al, bg[T].x, bg[T].y);
        }
#pragma unroll
        for (int T = 0; T < 12; T++) {
            int g = T >> 2;
            int col = g * 256 + 32 * j + 8 * (T & 3) + qc * 2;
            float b0 = b_ih[cam * Gn + col], b1 = b_ih[cam * Gn + col + 1];
            if (g < 2) { b0 += b_hh[cam * Gn + col]; b1 += b_hh[cam * Gn + col + 1]; }
            gi[4 * T] += b0; gi[4 * T + 1] += b1; gi[4 * T + 2] += b0; gi[4 * T + 3] += b1;
        }
    }
#pragma unroll
    for (int q = 0; q < 16; q++) hold[q] = 0.f;
    int bt = 0;

    for (int i = 0; i <= Tn; i++) {
        const int gateN = (i > 0 && i < Tn) ? 12 : 0;
        const int nT = gateN + ((i > 0) ? 8 : 0);
        const int U = na * nT;

        if (U > 0) {
            float acc[MAXU][4];
            int um[MAXU];                      // (mt<<8)|(T<<1)|isGate
            const uint4* ubp[MAXU];
            const int base = U >> 4, rem = U & 15;
            const int nu = base + (wid < rem ? 1 : 0);
            const int u0 = wid * base + (wid < rem ? wid : rem);
            const int mtA = u0 / nT;
            int qSplit = nu;
            {
                int mt = mtA, tt = u0 - mtA * nT;
#pragma unroll
                for (int q = 0; q < MAXU; q++) {
                    if (q < nu) {
                        int g = (tt < gateN) ? 1 : 0;
                        int T = g ? tt : tt - gateN;
                        um[q] = (mt << 8) | (T << 1) | g;
                        ubp[q] = (g ? sB : sBo) + (T * 16) * 32 + lane;
                        if (mt != mtA && q < qSplit) qSplit = q;
#pragma unroll
                        for (int z = 0; z < 4; z++) acc[q][z] = 0.f;
                    }
                    tt++; if (tt == nT) { tt = 0; mt++; }
                }
            }
            const uint32_t* hb = g_h + (size_t)((i & 1) * MAXG + grp) * 2 * 16384;
#pragma unroll 1
            for (int s = 0; s < 2; s++) {
                const int lo = s ? qSplit : 0, hi = s ? nu : qSplit;
                if (lo >= hi) continue;
                const int smt = mtA + s;
                const int r0 = 16 * smt + qr, r1 = r0 + 8;
                uint32_t ah[4], al[4], nh[4], nl[4];
                ldfrag(hb, qc, r0, r1, ah, al);
                for (int kc = 0; kc < 16; kc++) {
                    if (kc < 15) ldfrag(hb, qc + 8 * (kc + 1), r0, r1, nh, nl);
                    uint4 bfr[MAXU];
#pragma unroll
                    for (int q = 0; q < MAXU; q++) if (q >= lo && q < hi) bfr[q] = ubp[q][kc * 32];
#pragma unroll
                    for (int q = 0; q < MAXU; q++) if (q >= lo && q < hi) mma4(acc[q], ah, bfr[q].x, bfr[q].y);
#pragma unroll
                    for (int q = 0; q < MAXU; q++) if (q >= lo && q < hi) mma4(acc[q], ah, bfr[q].z, bfr[q].w);
#pragma unroll
                    for (int q = 0; q < MAXU; q++) if (q >= lo && q < hi) mma4(acc[q], al, bfr[q].x, bfr[q].y);
#pragma unroll
                    for (int q = 0; q < 4; q++) { ah[q] = nh[q]; al[q] = nl[q]; }
                }
            }
            // emit: gate units -> smem D; out units -> local epilogue
#pragma unroll
            for (int q = 0; q < MAXU; q++) if (q < nu) {
                int mt = um[q] >> 8, T = (um[q] >> 1) & 127;
                if (um[q] & 1) {
                    *(float4*)&dbuf[(size_t)(mt * 12 + T) * 128 + lane * 4] =
                        make_float4(acc[q][0], acc[q][1], acc[q][2], acc[q][3]);
                } else {
                    int cl = 8 * T + qc * 2, col = 64 * j + cl;
                    float b0 = bcs[cl], b1 = bcs[cl + 1];
                    int rr0 = 16 * mt + qr, rr1 = rr0 + 8;
                    if (rr0 < cnt) {
                        float* p = out + (size_t)samp[rr0] * OT + (size_t)col * Tn + (i - 1);
                        p[0] = sigf(acc[q][0] + b0); p[Tn] = sigf(acc[q][1] + b1);
                    }
                    if (rr1 < cnt) {
                        float* p = out + (size_t)samp[rr1] * OT + (size_t)col * Tn + (i - 1);
                        p[0] = sigf(acc[q][2] + b0); p[Tn] = sigf(acc[q][3] + b1);
                    }
                }
            }
        }
        if (gateN) __syncthreads();   // gate D staged

        if (i < Tn && epiAct) {       // gate epilogue -> h_{i+1}
            float gacc[48];
            if (i > 0) {
#pragma unroll
                for (int T = 0; T < 12; T++)
                    *(float4*)&gacc[4 * T] = *(const float4*)&dbuf[(size_t)(wid * 12 + T) * 128 + lane * 4];
            } else {
#pragma unroll
                for (int q = 0; q < 48; q++) gacc[q] = 0.f;
            }
            const int r0 = 16 * wid + qr, r1 = r0 + 8;
            uint32_t* dh = g_h + (size_t)(((i + 1) & 1) * MAXG + grp) * 2 * 16384;
#pragma unroll
            for (int tt = 0; tt < 4; tt++) {
                int cb = 8 * tt + qc * 2;
                float bn0 = bhs[cb], bn1 = bhs[cb + 1];
                float h0, h1, h2, h3;
                { float r = sigf(gi[4 * tt] + gacc[4 * tt]);
                  float z = sigf(gi[16 + 4 * tt] + gacc[16 + 4 * tt]);
                  float n = tanhf_(gi[32 + 4 * tt] + r * (gacc[32 + 4 * tt] + bn0));
                  h0 = (1.f - z) * n + z * hold[4 * tt]; hold[4 * tt] = h0; }
                { float r = sigf(gi[4 * tt + 1] + gacc[4 * tt + 1]);
                  float z = sigf(gi[16 + 4 * tt + 1] + gacc[16 + 4 * tt + 1]);
                  float n = tanhf_(gi[32 + 4 * tt + 1] + r * (gacc[32 + 4 * tt + 1] + bn1));
                  h1 = (1.f - z) * n + z * hold[4 * tt + 1]; hold[4 * tt + 1] = h1; }
                { float r = sigf(gi[4 * tt + 2] + gacc[4 * tt + 2]);
                  float z = sigf(gi[16 + 4 * tt + 2] + gacc[16 + 4 * tt + 2]);
                  float n = tanhf_(gi[32 + 4 * tt + 2] + r * (gacc[32 + 4 * tt + 2] + bn0));
                  h2 = (1.f - z) * n + z * hold[4 * tt + 2]; hold[4 * tt + 2] = h2; }
                { float r = sigf(gi[4 * tt + 3] + gacc[4 * tt + 3]);
                  float z = sigf(gi[16 + 4 * tt + 3] + gacc[16 + 4 * tt + 3]);
                  float n = tanhf_(gi[32 + 4 * tt + 3] + r * (gacc[32 + 4 * tt + 3] + bn1));
                  h3 = (1.f - z) * n + z * hold[4 * tt + 3]; hold[4 * tt + 3] = h3; }
                uint32_t w0h, w0l, w1h, w1l;
                bfsplit2(h0, h1, w0h, w0l);
                bfsplit2(h2, h3, w1h, w1l);
                int wrd = 16 * j + 4 * tt + qc;
                dh[r0 * 128 + wrd] = w0h; dh[r1 * 128 + wrd] = w1h;
                dh[16384 + r0 * 128 + wrd] = w0l; dh[16384 + r1 * 128 + wrd] = w1l;
            }
        }
        if (i < Tn) {   // per-group barrier (8 CTAs, all resident)
            __threadfence();
            __syncthreads();
            bt += 8;
            if (tid == 0) {
                atomicAdd(&g_bar[grp], 1);
                int v;
                do {
                    asm volatile("ld.global.acquire.gpu.b32 %0,[%1];" : "=r"(v) : "l"(&g_bar[grp]) : "memory");
                } while (v < bt);
            }
            __syncthreads();
        }
    }
}

// ---------------------------------------------------------------------------
extern "C" void kernel_launch(void* const* d_in, const int* in_sizes, int n_in,
                              void* d_out, int out_size) {
    const float* x    = (const float*)d_in[0];
    const int*   cam  = (const int*)  d_in[1];
    const float* W_ih = (const float*)d_in[2];
    const float* W_hh = (const float*)d_in[3];
    const float* b_ih = (const float*)d_in[4];
    const float* b_hh = (const float*)d_in[5];
    const float* Wc   = (const float*)d_in[6];
    const float* bc   = (const float*)d_in[7];
    float* out = (float*)d_out;
    // 10240 uint4 (163840) + 12288 floats D (49152) + tail 896 = 213888
    const int smem = 213888;
    cudaFuncSetAttribute(gru, cudaFuncAttributeMaxDynamicSharedMemorySize, smem);
    prep<<<1024, 256>>>(cam, W_ih, W_hh, Wc);
    gru<<<MAXG * 8, 512, smem>>>(x, b_ih, b_hh, bc, out);
}

// round 15
// speedup vs baseline: 1.1471x; 1.1471x over previous
#include <cuda_runtime.h>
#include <cuda_bf16.h>
#include <cstdint>

#define Bn 1024
#define Hn 256
#define Gn 768
#define On 512
#define Tn 60
#define Cc 15
#define MAXG 18
#define OT (On*Tn)
#define MAXU 20

__device__ __align__(16) uint4 g_Bw[120 * 6144];
__device__ __align__(16) uint4 g_Bo[120 * 4096];
__device__ __align__(16) uint4 g_Bx[120 * 6144];
__device__ __align__(16) uint32_t g_h[2 * MAXG * 2 * 16384];
__device__ int g_perm[Bn], g_gcam[MAXG], g_goff[MAXG], g_gcnt[MAXG], g_ngrp, g_bar[MAXG];

__device__ __forceinline__ float sigf(float v) { return 1.f / (1.f + __expf(-v)); }
__device__ __forceinline__ float tanhf_(float v) { return 2.f * sigf(2.f * v) - 1.f; }
__device__ __forceinline__ void bfsplit2(float f0, float f1, uint32_t& hi, uint32_t& lo) {
    unsigned short a = __bfloat16_as_ushort(__float2bfloat16_rn(f0));
    unsigned short b = __bfloat16_as_ushort(__float2bfloat16_rn(f1));
    float r0 = f0 - __uint_as_float((uint32_t)a << 16);
    float r1 = f1 - __uint_as_float((uint32_t)b << 16);
    unsigned short c = __bfloat16_as_ushort(__float2bfloat16_rn(r0));
    unsigned short d = __bfloat16_as_ushort(__float2bfloat16_rn(r1));
    hi = (uint32_t)a | ((uint32_t)b << 16);
    lo = (uint32_t)c | ((uint32_t)d << 16);
}
__device__ __forceinline__ void mma4(float* c, const uint32_t* a, uint32_t b0, uint32_t b1) {
    asm volatile("mma.sync.aligned.m16n8k16.row.col.f32.bf16.bf16.f32 "
                 "{%0,%1,%2,%3},{%4,%5,%6,%7},{%8,%9},{%0,%1,%2,%3};"
                 : "+f"(c[0]), "+f"(c[1]), "+f"(c[2]), "+f"(c[3])
                 : "r"(a[0]), "r"(a[1]), "r"(a[2]), "r"(a[3]), "r"(b0), "r"(b1));
}
__device__ __forceinline__ void ldfrag(const uint32_t* hb, int w0, int r0, int r1,
                                       uint32_t* ah, uint32_t* al) {
    ah[0] = hb[r0 * 128 + w0];             ah[1] = hb[r1 * 128 + w0];
    ah[2] = hb[r0 * 128 + w0 + 4];         ah[3] = hb[r1 * 128 + w0 + 4];
    al[0] = hb[16384 + r0 * 128 + w0];     al[1] = hb[16384 + r1 * 128 + w0];
    al[2] = hb[16384 + r0 * 128 + w0 + 4]; al[3] = hb[16384 + r1 * 128 + w0 + 4];
}

// ---------------------------------------------------------------------------
__global__ void prep(const int* __restrict__ cam, const float* __restrict__ Wi,
                     const float* __restrict__ Wh, const float* __restrict__ Wc) {
    if (blockIdx.x == 0) {
        __shared__ int cn[Cc], cu[Cc], co[Cc];
        int tid = threadIdx.x;
        if (tid < Cc) cn[tid] = 0;
        if (tid < MAXG) g_bar[tid] = 0;
        __syncthreads();
        for (int b = tid; b < Bn; b += blockDim.x) atomicAdd(&cn[cam[b]], 1);
        __syncthreads();
        if (tid == 0) {
            int o = 0;
            for (int c = 0; c < Cc; c++) { co[c] = o; cu[c] = o; o += cn[c]; }
            int g = 0;
            for (int c = 0; c < Cc; c++)
                for (int s = 0; s < cn[c] && g < MAXG; s += 128) {
                    g_gcam[g] = c; g_goff[g] = co[c] + s; g_gcnt[g] = min(128, cn[c] - s); g++;
                }
            g_ngrp = g;
        }
        __syncthreads();
        for (int b = tid; b < Bn; b += blockDim.x) { int p = atomicAdd(&cu[cam[b]], 1); g_perm[p] = b; }
    }
    int idx = blockIdx.x * blockDim.x + threadIdx.x, st = gridDim.x * blockDim.x;
    const int NWG = 120 * 12 * 512;
    for (int i = idx; i < NWG; i += st) {
        int lane = i & 31, kc = (i >> 5) & 15, T = (i >> 9) % 12, tile = i / (512 * 12);
        int c = tile >> 3, j = tile & 7;
        size_t row = (size_t)c * Gn + (T >> 2) * 256 + 32 * j + 8 * (T & 3) + (lane >> 2);
        int k0 = 16 * kc + (lane & 3) * 2;
        size_t o = (size_t)tile * 6144 + (T * 16 + kc) * 32 + lane;
        uint32_t h0, l0, h1, l1;
        const float* w = Wh + row * Hn;
        bfsplit2(w[k0], w[k0 + 1], h0, l0); bfsplit2(w[k0 + 8], w[k0 + 9], h1, l1);
        g_Bw[o] = make_uint4(h0, h1, l0, l1);
        w = Wi + row * Hn;
        bfsplit2(w[k0], w[k0 + 1], h0, l0); bfsplit2(w[k0 + 8], w[k0 + 9], h1, l1);
        g_Bx[o] = make_uint4(h0, h1, l0, l1);
    }
    const int NWO = 120 * 8 * 512;
    for (int i = idx; i < NWO; i += st) {
        int lane = i & 31, kc = (i >> 5) & 15, T = (i >> 9) & 7, tile = i / (512 * 8);
        int c = tile >> 3, j = tile & 7;
        const float* w = Wc + ((size_t)c * On + 64 * j + 8 * T + (lane >> 2)) * Hn;
        int k0 = 16 * kc + (lane & 3) * 2;
        uint32_t h0, l0, h1, l1;
        bfsplit2(w[k0], w[k0 + 1], h0, l0); bfsplit2(w[k0 + 8], w[k0 + 9], h1, l1);
        g_Bo[(size_t)tile * 4096 + (T * 16 + kc) * 32 + lane] = make_uint4(h0, h1, l0, l1);
    }
}

// ---------------------------------------------------------------------------
// 144 CTAs x 256 threads (8 warps, 255 regs). Each step, na*nT (mtile,T)
// units split evenly over 8 warps (<=2 mtile segments per warp, all static
// unroll). Out units: local epilogue+STG. Gate units: stage D in smem;
// warp wid then runs the gate epilogue for mtile wid (gi in registers).
// ---------------------------------------------------------------------------
__global__ void __launch_bounds__(256, 1)
gru(const float* __restrict__ x, const float* __restrict__ b_ih,
    const float* __restrict__ b_hh, const float* __restrict__ bc,
    float* __restrict__ out) {
    extern __shared__ __align__(16) uint4 sm4[];
    uint4* sB  = sm4;                        // 6144 uint4 (gate)   [off 0]
    float* dbuf = (float*)(sm4 + 10240);     // 12288 floats (D staging)
    float* bcs = dbuf + 12288;               // 64
    float* bhs = bcs + 64;                   // 32
    int* samp  = (int*)(bhs + 32);           // 128

    const int grp = blockIdx.x >> 3, j = blockIdx.x & 7;
    if (grp >= g_ngrp) return;
    const int cam = g_gcam[grp], off0 = g_goff[grp], cnt = g_gcnt[grp];
    const int tile = cam * 8 + j;
    const int tid = threadIdx.x, wid = tid >> 5, lane = tid & 31;
    const int qr = lane >> 2, qc = lane & 3;
    const int na = (cnt + 15) >> 4;

    if (tid < 128) samp[tid] = (tid < cnt) ? g_perm[off0 + tid] : 0;
    if (tid < 64) bcs[tid] = bc[cam * On + 64 * j + tid];
    if (tid < 32) bhs[tid] = b_hh[cam * Gn + 512 + 32 * j + tid];
    {
        const uint4* s = g_Bw + (size_t)tile * 6144;
        for (int i = tid; i < 6144; i += 256) sB[i] = s[i];
        const uint4* s2 = g_Bo + (size_t)tile * 4096;
        for (int i = tid; i < 4096; i += 256) sm4[6144 + i] = s2[i];
    }
    __syncthreads();

    const bool epiAct = wid < na;
    float gi[48], hold[16];
    if (epiAct) {  // gi = x@Wi + biases (warp wid owns m-tile wid)
#pragma unroll
        for (int q = 0; q < 48; q++) gi[q] = 0.f;
        const int r0 = 16 * wid + qr, r1 = r0 + 8;
        const uint4* bx = g_Bx + (size_t)tile * 6144;
        const float* x0 = (r0 < cnt) ? x + (size_t)samp[r0] * Hn : 0;
        const float* x1 = (r1 < cnt) ? x + (size_t)samp[r1] * Hn : 0;
        for (int kc = 0; kc < 16; kc++) {
            int k0 = 16 * kc + qc * 2;
            float2 p00 = x0 ? *(const float2*)(x0 + k0) : make_float2(0.f, 0.f);
            float2 p02 = x0 ? *(const float2*)(x0 + k0 + 8) : make_float2(0.f, 0.f);
            float2 p10 = x1 ? *(const float2*)(x1 + k0) : make_float2(0.f, 0.f);
            float2 p12 = x1 ? *(const float2*)(x1 + k0 + 8) : make_float2(0.f, 0.f);
            uint32_t ah[4], al[4];
            bfsplit2(p00.x, p00.y, ah[0], al[0]);
            bfsplit2(p10.x, p10.y, ah[1], al[1]);
            bfsplit2(p02.x, p02.y, ah[2], al[2]);
            bfsplit2(p12.x, p12.y, ah[3], al[3]);
            uint4 bg[12];
#pragma unroll
            for (int T = 0; T < 12; T++) bg[T] = bx[(T * 16 + kc) * 32 + lane];
#pragma unroll
            for (int T = 0; T < 12; T++) mma4(gi + 4 * T, ah, bg[T].x, bg[T].y);
#pragma unroll
            for (int T = 0; T < 12; T++) mma4(gi + 4 * T, ah, bg[T].z, bg[T].w);
#pragma unroll
            for (int T = 0; T < 12; T++) mma4(gi + 4 * T, al, bg[T].x, bg[T].y);
        }
#pragma unroll
        for (int T = 0; T < 12; T++) {
            int g = T >> 2;
            int col = g * 256 + 32 * j + 8 * (T & 3) + qc * 2;
            float b0 = b_ih[cam * Gn + col], b1 = b_ih[cam * Gn + col + 1];
            if (g < 2) { b0 += b_hh[cam * Gn + col]; b1 += b_hh[cam * Gn + col + 1]; }
            gi[4 * T] += b0; gi[4 * T + 1] += b1; gi[4 * T + 2] += b0; gi[4 * T + 3] += b1;
        }
    }
#pragma unroll
    for (int q = 0; q < 16; q++) hold[q] = 0.f;
    int bt = 0;

    for (int i = 0; i <= Tn; i++) {
        const int gateN = (i > 0 && i < Tn) ? 12 : 0;
        const int nT = gateN + ((i > 0) ? 8 : 0);
        const int U = na * nT;

        if (U > 0) {
            const int base = U >> 3, rem = U & 7;
            const int nu = base + (wid < rem ? 1 : 0);
            const int u0 = wid * base + (wid < rem ? wid : rem);
            const int mtA = u0 / nT;
            // per-unit decode (static arrays, unrolled)
            int umt[MAXU], uT[MAXU], uoff[MAXU];
            bool ug[MAXU];
            int qSplit = nu;
            {
                int mt = mtA, tt = u0 - mtA * nT;
                bool found = false;
#pragma unroll
                for (int q = 0; q < MAXU; q++) {
                    bool g = tt < gateN;
                    int T = g ? tt : tt - gateN;
                    umt[q] = mt; uT[q] = T; ug[q] = g;
                    uoff[q] = (g ? 0 : 6144) + T * 512 + lane;   // uint4 idx, +kc*32
                    if (q < nu && mt != mtA && !found) { qSplit = q; found = true; }
                    tt++; if (tt == nT) { tt = 0; mt++; }
                }
            }
            float acc[MAXU][4];
#pragma unroll
            for (int q = 0; q < MAXU; q++) {
                acc[q][0] = 0.f; acc[q][1] = 0.f; acc[q][2] = 0.f; acc[q][3] = 0.f;
            }
            const uint32_t* hb = g_h + (size_t)((i & 1) * MAXG + grp) * 2 * 16384;
#pragma unroll 1
            for (int s = 0; s < 2; s++) {
                const int lo = s ? qSplit : 0, hi = s ? nu : qSplit;
                if (lo >= hi) continue;
                const int smt = mtA + s;
                const int r0 = 16 * smt + qr, r1 = r0 + 8;
                uint32_t ah[4], al[4], nh[4], nl[4];
                ldfrag(hb, qc, r0, r1, ah, al);
                for (int kc = 0; kc < 16; kc++) {
                    if (kc < 15) ldfrag(hb, qc + 8 * (kc + 1), r0, r1, nh, nl);
                    const int ko = kc * 32;
#pragma unroll
                    for (int c = 0; c < 4; c++) {   // chunks of 6 units
                        uint4 bfr[6];
#pragma unroll
                        for (int e = 0; e < 6; e++) {
                            int q = 6 * c + e;
                            if (q >= lo && q < hi) bfr[e] = sm4[uoff[q] + ko];
                        }
#pragma unroll
                        for (int e = 0; e < 6; e++) {
                            int q = 6 * c + e;
                            if (q >= lo && q < hi) mma4(acc[q], ah, bfr[e].x, bfr[e].y);
                        }
#pragma unroll
                        for (int e = 0; e < 6; e++) {
                            int q = 6 * c + e;
                            if (q >= lo && q < hi) mma4(acc[q], ah, bfr[e].z, bfr[e].w);
                        }
#pragma unroll
                        for (int e = 0; e < 6; e++) {
                            int q = 6 * c + e;
                            if (q >= lo && q < hi) mma4(acc[q], al, bfr[e].x, bfr[e].y);
                        }
                    }
#pragma unroll
                    for (int q = 0; q < 4; q++) { ah[q] = nh[q]; al[q] = nl[q]; }
                }
            }
            // emit: gate units -> smem D; out units -> local epilogue + STG
#pragma unroll
            for (int q = 0; q < MAXU; q++) if (q < nu) {
                int mt = umt[q], T = uT[q];
                if (ug[q]) {
                    *(float4*)&dbuf[(size_t)(mt * 12 + T) * 128 + lane * 4] =
                        make_float4(acc[q][0], acc[q][1], acc[q][2], acc[q][3]);
                } else {
                    int cl = 8 * T + qc * 2, col = 64 * j + cl;
                    float b0 = bcs[cl], b1 = bcs[cl + 1];
                    int rr0 = 16 * mt + qr, rr1 = rr0 + 8;
                    if (rr0 < cnt) {
                        float* p = out + (size_t)samp[rr0] * OT + (size_t)col * Tn + (i - 1);
                        p[0] = sigf(acc[q][0] + b0); p[Tn] = sigf(acc[q][1] + b1);
                    }
                    if (rr1 < cnt) {
                        float* p = out + (size_t)samp[rr1] * OT + (size_t)col * Tn + (i - 1);
                        p[0] = sigf(acc[q][2] + b0); p[Tn] = sigf(acc[q][3] + b1);
                    }
                }
            }
        }
        if (gateN) __syncthreads();   // gate D staged

        if (i < Tn && epiAct) {       // gate epilogue -> h_{i+1}
            float gacc[48];
            if (i > 0) {
#pragma unroll
                for (int T = 0; T < 12; T++)
                    *(float4*)&gacc[4 * T] = *(const float4*)&dbuf[(size_t)(wid * 12 + T) * 128 + lane * 4];
            } else {
#pragma unroll
                for (int q = 0; q < 48; q++) gacc[q] = 0.f;
            }
            const int r0 = 16 * wid + qr, r1 = r0 + 8;
            uint32_t* dh = g_h + (size_t)(((i + 1) & 1) * MAXG + grp) * 2 * 16384;
#pragma unroll
            for (int tt = 0; tt < 4; tt++) {
                int cb = 8 * tt + qc * 2;
                float bn0 = bhs[cb], bn1 = bhs[cb + 1];
                float h0, h1, h2, h3;
                { float r = sigf(gi[4 * tt] + gacc[4 * tt]);
                  float z = sigf(gi[16 + 4 * tt] + gacc[16 + 4 * tt]);
                  float n = tanhf_(gi[32 + 4 * tt] + r * (gacc[32 + 4 * tt] + bn0));
                  h0 = (1.f - z) * n + z * hold[4 * tt]; hold[4 * tt] = h0; }
                { float r = sigf(gi[4 * tt + 1] + gacc[4 * tt + 1]);
                  float z = sigf(gi[16 + 4 * tt + 1] + gacc[16 + 4 * tt + 1]);
                  float n = tanhf_(gi[32 + 4 * tt + 1] + r * (gacc[32 + 4 * tt + 1] + bn1));
                  h1 = (1.f - z) * n + z * hold[4 * tt + 1]; hold[4 * tt + 1] = h1; }
                { float r = sigf(gi[4 * tt + 2] + gacc[4 * tt + 2]);
                  float z = sigf(gi[16 + 4 * tt + 2] + gacc[16 + 4 * tt + 2]);
                  float n = tanhf_(gi[32 + 4 * tt + 2] + r * (gacc[32 + 4 * tt + 2] + bn0));
                  h2 = (1.f - z) * n + z * hold[4 * tt + 2]; hold[4 * tt + 2] = h2; }
                { float r = sigf(gi[4 * tt + 3] + gacc[4 * tt + 3]);
                  float z = sigf(gi[16 + 4 * tt + 3] + gacc[16 + 4 * tt + 3]);
                  float n = tanhf_(gi[32 + 4 * tt + 3] + r * (gacc[32 + 4 * tt + 3] + bn1));
                  h3 = (1.f - z) * n + z * hold[4 * tt + 3]; hold[4 * tt + 3] = h3; }
                uint32_t w0h, w0l, w1h, w1l;
                bfsplit2(h0, h1, w0h, w0l);
                bfsplit2(h2, h3, w1h, w1l);
                int wrd = 16 * j + 4 * tt + qc;
                dh[r0 * 128 + wrd] = w0h; dh[r1 * 128 + wrd] = w1h;
                dh[16384 + r0 * 128 + wrd] = w0l; dh[16384 + r1 * 128 + wrd] = w1l;
            }
        }
        if (i < Tn) {   // per-group barrier (8 CTAs, all resident)
            __threadfence();
            __syncthreads();
            bt += 8;
            if (tid == 0) {
                atomicAdd(&g_bar[grp], 1);
                int v;
                do {
                    asm volatile("ld.global.acquire.gpu.b32 %0,[%1];" : "=r"(v) : "l"(&g_bar[grp]) : "memory");
                } while (v < bt);
            }
            __syncthreads();
        }
    }
}

// ---------------------------------------------------------------------------
extern "C" void kernel_launch(void* const* d_in, const int* in_sizes, int n_in,
                              void* d_out, int out_size) {
    const float* x    = (const float*)d_in[0];
    const int*   cam  = (const int*)  d_in[1];
    const float* W_ih = (const float*)d_in[2];
    const float* W_hh = (const float*)d_in[3];
    const float* b_ih = (const float*)d_in[4];
    const float* b_hh = (const float*)d_in[5];
    const float* Wc   = (const float*)d_in[6];
    const float* bc   = (const float*)d_in[7];
    float* out = (float*)d_out;
    // 10240 uint4 (163840) + 12288 floats (49152) + tail 896 = 213888
    const int smem = 213888;
    cudaFuncSetAttribute(gru, cudaFuncAttributeMaxDynamicSharedMemorySize, smem);
    prep<<<1024, 256>>>(cam, W_ih, W_hh, Wc);
    gru<<<MAXG * 8, 256, smem>>>(x, b_ih, b_hh, bc, out);
}

// round 16
// speedup vs baseline: 2.0061x; 1.7488x over previous
#include <cuda_runtime.h>
#include <cuda_bf16.h>
#include <cstdint>

#define Bn 1024
#define Hn 256
#define Gn 768
#define On 512
#define Tn 60
#define Cc 15
#define MAXG 18
#define OT (On*Tn)

// B fragments as uint4 (bh0,bh1,bl0,bl1), fragment-ordered
__device__ __align__(16) uint4 g_Bw[120 * 6144];   // gate: 12T x 16kc x 32lane
__device__ __align__(16) uint4 g_Bo[120 * 4096];   // out:   8T x 16kc x 32lane
__device__ __align__(16) uint4 g_Bx[120 * 6144];   // Wi
__device__ __align__(16) uint32_t g_h[2 * MAXG * 2 * 16384];
__device__ int g_perm[Bn], g_gcam[MAXG], g_goff[MAXG], g_gcnt[MAXG], g_ngrp, g_bar[MAXG];

__device__ __forceinline__ float sigf(float v) { return 1.f / (1.f + __expf(-v)); }
__device__ __forceinline__ float tanhf_(float v) { return 2.f * sigf(2.f * v) - 1.f; }
__device__ __forceinline__ void bfsplit2(float f0, float f1, uint32_t& hi, uint32_t& lo) {
    unsigned short a = __bfloat16_as_ushort(__float2bfloat16_rn(f0));
    unsigned short b = __bfloat16_as_ushort(__float2bfloat16_rn(f1));
    float r0 = f0 - __uint_as_float((uint32_t)a << 16);
    float r1 = f1 - __uint_as_float((uint32_t)b << 16);
    unsigned short c = __bfloat16_as_ushort(__float2bfloat16_rn(r0));
    unsigned short d = __bfloat16_as_ushort(__float2bfloat16_rn(r1));
    hi = (uint32_t)a | ((uint32_t)b << 16);
    lo = (uint32_t)c | ((uint32_t)d << 16);
}
__device__ __forceinline__ void mma4(float* c, const uint32_t* a, uint32_t b0, uint32_t b1) {
    asm volatile("mma.sync.aligned.m16n8k16.row.col.f32.bf16.bf16.f32 "
                 "{%0,%1,%2,%3},{%4,%5,%6,%7},{%8,%9},{%0,%1,%2,%3};"
                 : "+f"(c[0]), "+f"(c[1]), "+f"(c[2]), "+f"(c[3])
                 : "r"(a[0]), "r"(a[1]), "r"(a[2]), "r"(a[3]), "r"(b0), "r"(b1));
}
__device__ __forceinline__ void ldfrag(const uint32_t* hb, int w0, int r0, int r1,
                                       uint32_t* ah, uint32_t* al) {
    ah[0] = hb[r0 * 128 + w0];             ah[1] = hb[r1 * 128 + w0];
    ah[2] = hb[r0 * 128 + w0 + 4];         ah[3] = hb[r1 * 128 + w0 + 4];
    al[0] = hb[16384 + r0 * 128 + w0];     al[1] = hb[16384 + r1 * 128 + w0];
    al[2] = hb[16384 + r0 * 128 + w0 + 4]; al[3] = hb[16384 + r1 * 128 + w0 + 4];
}

// ---------------------------------------------------------------------------
__global__ void prep(const int* __restrict__ cam, const float* __restrict__ Wi,
                     const float* __restrict__ Wh, const float* __restrict__ Wc) {
    if (blockIdx.x == 0) {
        __shared__ int cn[Cc], cu[Cc], co[Cc];
        int tid = threadIdx.x;
        if (tid < Cc) cn[tid] = 0;
        if (tid < MAXG) g_bar[tid] = 0;
        __syncthreads();
        for (int b = tid; b < Bn; b += blockDim.x) atomicAdd(&cn[cam[b]], 1);
        __syncthreads();
        if (tid == 0) {
            int o = 0;
            for (int c = 0; c < Cc; c++) { co[c] = o; cu[c] = o; o += cn[c]; }
            int g = 0;
            for (int c = 0; c < Cc; c++)
                for (int s = 0; s < cn[c] && g < MAXG; s += 128) {
                    g_gcam[g] = c; g_goff[g] = co[c] + s; g_gcnt[g] = min(128, cn[c] - s); g++;
                }
            g_ngrp = g;
        }
        __syncthreads();
        for (int b = tid; b < Bn; b += blockDim.x) { int p = atomicAdd(&cu[cam[b]], 1); g_perm[p] = b; }
    }
    int idx = blockIdx.x * blockDim.x + threadIdx.x, st = gridDim.x * blockDim.x;
    const int NWG = 120 * 12 * 512;
    for (int i = idx; i < NWG; i += st) {
        int lane = i & 31, kc = (i >> 5) & 15, T = (i >> 9) % 12, tile = i / (512 * 12);
        int c = tile >> 3, j = tile & 7;
        size_t row = (size_t)c * Gn + (T >> 2) * 256 + 32 * j + 8 * (T & 3) + (lane >> 2);
        int k0 = 16 * kc + (lane & 3) * 2;
        size_t o = (size_t)tile * 6144 + (T * 16 + kc) * 32 + lane;
        uint32_t h0, l0, h1, l1;
        const float* w = Wh + row * Hn;
        bfsplit2(w[k0], w[k0 + 1], h0, l0); bfsplit2(w[k0 + 8], w[k0 + 9], h1, l1);
        g_Bw[o] = make_uint4(h0, h1, l0, l1);
        w = Wi + row * Hn;
        bfsplit2(w[k0], w[k0 + 1], h0, l0); bfsplit2(w[k0 + 8], w[k0 + 9], h1, l1);
        g_Bx[o] = make_uint4(h0, h1, l0, l1);
    }
    const int NWO = 120 * 8 * 512;
    for (int i = idx; i < NWO; i += st) {
        int lane = i & 31, kc = (i >> 5) & 15, T = (i >> 9) & 7, tile = i / (512 * 8);
        int c = tile >> 3, j = tile & 7;
        const float* w = Wc + ((size_t)c * On + 64 * j + 8 * T + (lane >> 2)) * Hn;
        int k0 = 16 * kc + (lane & 3) * 2;
        uint32_t h0, l0, h1, l1;
        bfsplit2(w[k0], w[k0 + 1], h0, l0); bfsplit2(w[k0 + 8], w[k0 + 9], h1, l1);
        g_Bo[(size_t)tile * 4096 + (T * 16 + kc) * 32 + lane] = make_uint4(h0, h1, l0, l1);
    }
}

// ---------------------------------------------------------------------------
// 144 CTAs x 256 threads (8 warps). Role split:
//  gate warps (wid < na): own tile's 12 gate units -> gacc regs -> epilogue.
//  out warps (wid >= na): whole tiles m = wid-na, +nIdle,... (8 out units
//  each, oacc[32] reused per tile, no guards in hot loop).
//  Fallback (na >= 7): gate warps also do own-tile out (exact R13 path).
// ---------------------------------------------------------------------------
__global__ void __launch_bounds__(256, 1)
gru(const float* __restrict__ x, const float* __restrict__ b_ih,
    const float* __restrict__ b_hh, const float* __restrict__ bc,
    float* __restrict__ out) {
    extern __shared__ __align__(16) uint4 sm4[];
    uint4* sB  = sm4;                        // 6144 uint4 (gate)
    uint4* sBo = sm4 + 6144;                 // 4096 uint4 (out)
    float* bcs = (float*)(sm4 + 10240);      // 64
    float* bhs = bcs + 64;                   // 32
    int* samp  = (int*)(bhs + 32);           // 128

    const int grp = blockIdx.x >> 3, j = blockIdx.x & 7;
    if (grp >= g_ngrp) return;
    const int cam = g_gcam[grp], off0 = g_goff[grp], cnt = g_gcnt[grp];
    const int tile = cam * 8 + j;
    const int tid = threadIdx.x, wid = tid >> 5, lane = tid & 31;
    const int qr = lane >> 2, qc = lane & 3;
    const int na = (cnt + 15) >> 4;
    const int nIdle = 8 - na;
    const bool gateDoesOut = (na > 3 * nIdle);   // na >= 7
    const bool epiAct = wid < na;

    if (tid < 128) samp[tid] = (tid < cnt) ? g_perm[off0 + tid] : 0;
    if (tid < 64) bcs[tid] = bc[cam * On + 64 * j + tid];
    if (tid < 32) bhs[tid] = b_hh[cam * Gn + 512 + 32 * j + tid];
    {
        const uint4* s = g_Bw + (size_t)tile * 6144;
        for (int i = tid; i < 6144; i += 256) sB[i] = s[i];
        const uint4* s2 = g_Bo + (size_t)tile * 4096;
        for (int i = tid; i < 4096; i += 256) sBo[i] = s2[i];
    }
    __syncthreads();

    float gi[48], hold[16];
    if (epiAct) {  // gi = x@Wi + biases (warp wid owns m-tile wid)
#pragma unroll
        for (int q = 0; q < 48; q++) gi[q] = 0.f;
        const int r0 = 16 * wid + qr, r1 = r0 + 8;
        const uint4* bx = g_Bx + (size_t)tile * 6144;
        const float* x0 = (r0 < cnt) ? x + (size_t)samp[r0] * Hn : 0;
        const float* x1 = (r1 < cnt) ? x + (size_t)samp[r1] * Hn : 0;
        for (int kc = 0; kc < 16; kc++) {
            int k0 = 16 * kc + qc * 2;
            float2 p00 = x0 ? *(const float2*)(x0 + k0) : make_float2(0.f, 0.f);
            float2 p02 = x0 ? *(const float2*)(x0 + k0 + 8) : make_float2(0.f, 0.f);
            float2 p10 = x1 ? *(const float2*)(x1 + k0) : make_float2(0.f, 0.f);
            float2 p12 = x1 ? *(const float2*)(x1 + k0 + 8) : make_float2(0.f, 0.f);
            uint32_t ah[4], al[4];
            bfsplit2(p00.x, p00.y, ah[0], al[0]);
            bfsplit2(p10.x, p10.y, ah[1], al[1]);
            bfsplit2(p02.x, p02.y, ah[2], al[2]);
            bfsplit2(p12.x, p12.y, ah[3], al[3]);
            uint4 bg[12];
#pragma unroll
            for (int T = 0; T < 12; T++) bg[T] = bx[(T * 16 + kc) * 32 + lane];
#pragma unroll
            for (int T = 0; T < 12; T++) mma4(gi + 4 * T, ah, bg[T].x, bg[T].y);
#pragma unroll
            for (int T = 0; T < 12; T++) mma4(gi + 4 * T, ah, bg[T].z, bg[T].w);
#pragma unroll
            for (int T = 0; T < 12; T++) mma4(gi + 4 * T, al, bg[T].x, bg[T].y);
        }
#pragma unroll
        for (int T = 0; T < 12; T++) {
            int g = T >> 2;
            int col = g * 256 + 32 * j + 8 * (T & 3) + qc * 2;
            float b0 = b_ih[cam * Gn + col], b1 = b_ih[cam * Gn + col + 1];
            if (g < 2) { b0 += b_hh[cam * Gn + col]; b1 += b_hh[cam * Gn + col + 1]; }
            gi[4 * T] += b0; gi[4 * T + 1] += b1; gi[4 * T + 2] += b0; gi[4 * T + 3] += b1;
        }
    }
#pragma unroll
    for (int q = 0; q < 16; q++) hold[q] = 0.f;
    int bt = 0;

    for (int i = 0; i <= Tn; i++) {
        float gacc[48];
#pragma unroll
        for (int q = 0; q < 48; q++) gacc[q] = 0.f;

        if (i > 0) {
            const uint32_t* hb = g_h + (size_t)((i & 1) * MAXG + grp) * 2 * 16384;
            if (epiAct) {
                // ---- gate warp: 12 gate units (+ own out if fallback) ----
                const bool dog = i < Tn;
                const bool doo = gateDoesOut;
                if (dog || doo) {
                    float oacc[32];
#pragma unroll
                    for (int q = 0; q < 32; q++) oacc[q] = 0.f;
                    const int r0 = 16 * wid + qr, r1 = r0 + 8;
                    uint32_t ah[4], al[4], nh[4], nl[4];
                    ldfrag(hb, qc, r0, r1, ah, al);
                    for (int kc = 0; kc < 16; kc++) {
                        if (kc < 15) ldfrag(hb, qc + 8 * (kc + 1), r0, r1, nh, nl);
                        if (dog) {
                            uint4 bg[12];
#pragma unroll
                            for (int T = 0; T < 12; T++) bg[T] = sB[(T * 16 + kc) * 32 + lane];
#pragma unroll
                            for (int T = 0; T < 12; T++) mma4(gacc + 4 * T, ah, bg[T].x, bg[T].y);
#pragma unroll
                            for (int T = 0; T < 12; T++) mma4(gacc + 4 * T, ah, bg[T].z, bg[T].w);
#pragma unroll
                            for (int T = 0; T < 12; T++) mma4(gacc + 4 * T, al, bg[T].x, bg[T].y);
                        }
                        if (doo) {
                            uint4 bo[8];
#pragma unroll
                            for (int T = 0; T < 8; T++) bo[T] = sBo[(T * 16 + kc) * 32 + lane];
#pragma unroll
                            for (int T = 0; T < 8; T++) mma4(oacc + 4 * T, ah, bo[T].x, bo[T].y);
#pragma unroll
                            for (int T = 0; T < 8; T++) mma4(oacc + 4 * T, ah, bo[T].z, bo[T].w);
#pragma unroll
                            for (int T = 0; T < 8; T++) mma4(oacc + 4 * T, al, bo[T].x, bo[T].y);
                        }
#pragma unroll
                        for (int q = 0; q < 4; q++) { ah[q] = nh[q]; al[q] = nl[q]; }
                    }
                    if (doo) {  // own-tile out epilogue (fallback path)
#pragma unroll
                        for (int ot = 0; ot < 8; ot++) {
                            int cl = 8 * ot + qc * 2, col = 64 * j + cl;
                            float b0 = bcs[cl], b1 = bcs[cl + 1];
                            if (r0 < cnt) {
                                float* p = out + (size_t)samp[r0] * OT + (size_t)col * Tn + (i - 1);
                                p[0] = sigf(oacc[4 * ot] + b0); p[Tn] = sigf(oacc[4 * ot + 1] + b1);
                            }
                            if (r1 < cnt) {
                                float* p = out + (size_t)samp[r1] * OT + (size_t)col * Tn + (i - 1);
                                p[0] = sigf(oacc[4 * ot + 2] + b0); p[Tn] = sigf(oacc[4 * ot + 3] + b1);
                            }
                        }
                    }
                }
            } else if (!gateDoesOut) {
                // ---- out warp: whole tiles m = wid-na, +nIdle, ... ----
                for (int m = wid - na; m < na; m += nIdle) {
                    float oacc[32];
#pragma unroll
                    for (int q = 0; q < 32; q++) oacc[q] = 0.f;
                    const int r0 = 16 * m + qr, r1 = r0 + 8;
                    uint32_t ah[4], al[4], nh[4], nl[4];
                    ldfrag(hb, qc, r0, r1, ah, al);
                    for (int kc = 0; kc < 16; kc++) {
                        if (kc < 15) ldfrag(hb, qc + 8 * (kc + 1), r0, r1, nh, nl);
                        uint4 bo[8];
#pragma unroll
                        for (int T = 0; T < 8; T++) bo[T] = sBo[(T * 16 + kc) * 32 + lane];
#pragma unroll
                        for (int T = 0; T < 8; T++) mma4(oacc + 4 * T, ah, bo[T].x, bo[T].y);
#pragma unroll
                        for (int T = 0; T < 8; T++) mma4(oacc + 4 * T, ah, bo[T].z, bo[T].w);
#pragma unroll
                        for (int T = 0; T < 8; T++) mma4(oacc + 4 * T, al, bo[T].x, bo[T].y);
#pragma unroll
                        for (int q = 0; q < 4; q++) { ah[q] = nh[q]; al[q] = nl[q]; }
                    }
#pragma unroll
                    for (int ot = 0; ot < 8; ot++) {
                        int cl = 8 * ot + qc * 2, col = 64 * j + cl;
                        float b0 = bcs[cl], b1 = bcs[cl + 1];
                        if (r0 < cnt) {
                            float* p = out + (size_t)samp[r0] * OT + (size_t)col * Tn + (i - 1);
                            p[0] = sigf(oacc[4 * ot] + b0); p[Tn] = sigf(oacc[4 * ot + 1] + b1);
                        }
                        if (r1 < cnt) {
                            float* p = out + (size_t)samp[r1] * OT + (size_t)col * Tn + (i - 1);
                            p[0] = sigf(oacc[4 * ot + 2] + b0); p[Tn] = sigf(oacc[4 * ot + 3] + b1);
                        }
                    }
                }
            }
        }
        if (i < Tn && epiAct) {  // gate epilogue -> h_{i+1}
            const int r0 = 16 * wid + qr, r1 = r0 + 8;
            uint32_t* dh = g_h + (size_t)(((i + 1) & 1) * MAXG + grp) * 2 * 16384;
#pragma unroll
            for (int tt = 0; tt < 4; tt++) {
                int cb = 8 * tt + qc * 2;
                float bn0 = bhs[cb], bn1 = bhs[cb + 1];
                float h0, h1, h2, h3;
                { float r = sigf(gi[4 * tt] + gacc[4 * tt]);
                  float z = sigf(gi[16 + 4 * tt] + gacc[16 + 4 * tt]);
                  float n = tanhf_(gi[32 + 4 * tt] + r * (gacc[32 + 4 * tt] + bn0));
                  h0 = (1.f - z) * n + z * hold[4 * tt]; hold[4 * tt] = h0; }
                { float r = sigf(gi[4 * tt + 1] + gacc[4 * tt + 1]);
                  float z = sigf(gi[16 + 4 * tt + 1] + gacc[16 + 4 * tt + 1]);
                  float n = tanhf_(gi[32 + 4 * tt + 1] + r * (gacc[32 + 4 * tt + 1] + bn1));
                  h1 = (1.f - z) * n + z * hold[4 * tt + 1]; hold[4 * tt + 1] = h1; }
                { float r = sigf(gi[4 * tt + 2] + gacc[4 * tt + 2]);
                  float z = sigf(gi[16 + 4 * tt + 2] + gacc[16 + 4 * tt + 2]);
                  float n = tanhf_(gi[32 + 4 * tt + 2] + r * (gacc[32 + 4 * tt + 2] + bn0));
                  h2 = (1.f - z) * n + z * hold[4 * tt + 2]; hold[4 * tt + 2] = h2; }
                { float r = sigf(gi[4 * tt + 3] + gacc[4 * tt + 3]);
                  float z = sigf(gi[16 + 4 * tt + 3] + gacc[16 + 4 * tt + 3]);
                  float n = tanhf_(gi[32 + 4 * tt + 3] + r * (gacc[32 + 4 * tt + 3] + bn1));
                  h3 = (1.f - z) * n + z * hold[4 * tt + 3]; hold[4 * tt + 3] = h3; }
                uint32_t w0h, w0l, w1h, w1l;
                bfsplit2(h0, h1, w0h, w0l);
                bfsplit2(h2, h3, w1h, w1l);
                int wrd = 16 * j + 4 * tt + qc;
                dh[r0 * 128 + wrd] = w0h; dh[r1 * 128 + wrd] = w1h;
                dh[16384 + r0 * 128 + wrd] = w0l; dh[16384 + r1 * 128 + wrd] = w1l;
            }
        }
        if (i < Tn) {   // per-group barrier (8 CTAs, all resident)
            __threadfence();
            __syncthreads();
            bt += 8;
            if (tid == 0) {
                atomicAdd(&g_bar[grp], 1);
                int v;
                do {
                    asm volatile("ld.global.acquire.gpu.b32 %0,[%1];" : "=r"(v) : "l"(&g_bar[grp]) : "memory");
                } while (v < bt);
            }
            __syncthreads();
        }
    }
}

// ---------------------------------------------------------------------------
extern "C" void kernel_launch(void* const* d_in, const int* in_sizes, int n_in,
                              void* d_out, int out_size) {
    const float* x    = (const float*)d_in[0];
    const int*   cam  = (const int*)  d_in[1];
    const float* W_ih = (const float*)d_in[2];
    const float* W_hh = (const float*)d_in[3];
    const float* b_ih = (const float*)d_in[4];
    const float* b_hh = (const float*)d_in[5];
    const float* Wc   = (const float*)d_in[6];
    const float* bc   = (const float*)d_in[7];
    float* out = (float*)d_out;
    // 10240 uint4 (163840) + 64f + 32f + 128i (896) = 164736, padded
    const int smem = 164864;
    cudaFuncSetAttribute(gru, cudaFuncAttributeMaxDynamicSharedMemorySize, smem);
    prep<<<1024, 256>>>(cam, W_ih, W_hh, Wc);
    gru<<<MAXG * 8, 256, smem>>>(x, b_ih, b_hh, bc, out);
}

// round 17
// speedup vs baseline: 2.3861x; 1.1895x over previous
#include <cuda_runtime.h>
#include <cuda_bf16.h>
#include <cstdint>

#define Bn 1024
#define Hn 256
#define Gn 768
#define On 512
#define Tn 60
#define Cc 15
#define MAXG 18
#define NS 16
#define OT (On*Tn)

// B fragments as uint4 (bh0,bh1,bl0,bl1), fragment-ordered. 240 tiles.
__device__ __align__(16) uint4 g_Bw[240 * 3072];   // gate: 6T x 16kc x 32lane
__device__ __align__(16) uint4 g_Bo[240 * 2048];   // out:  4T x 16kc x 32lane
__device__ __align__(16) uint4 g_Bx[240 * 3072];   // Wi
__device__ __align__(16) uint32_t g_h[2 * MAXG * 2 * 16384];
__device__ int g_perm[Bn], g_gcam[MAXG], g_goff[MAXG], g_gcnt[MAXG], g_ngrp, g_bar[MAXG];

__device__ __forceinline__ float sigf(float v) { return 1.f / (1.f + __expf(-v)); }
__device__ __forceinline__ float tanhf_(float v) { return 2.f * sigf(2.f * v) - 1.f; }
__device__ __forceinline__ void bfsplit2(float f0, float f1, uint32_t& hi, uint32_t& lo) {
    unsigned short a = __bfloat16_as_ushort(__float2bfloat16_rn(f0));
    unsigned short b = __bfloat16_as_ushort(__float2bfloat16_rn(f1));
    float r0 = f0 - __uint_as_float((uint32_t)a << 16);
    float r1 = f1 - __uint_as_float((uint32_t)b << 16);
    unsigned short c = __bfloat16_as_ushort(__float2bfloat16_rn(r0));
    unsigned short d = __bfloat16_as_ushort(__float2bfloat16_rn(r1));
    hi = (uint32_t)a | ((uint32_t)b << 16);
    lo = (uint32_t)c | ((uint32_t)d << 16);
}
__device__ __forceinline__ void mma4(float* c, const uint32_t* a, uint32_t b0, uint32_t b1) {
    asm volatile("mma.sync.aligned.m16n8k16.row.col.f32.bf16.bf16.f32 "
                 "{%0,%1,%2,%3},{%4,%5,%6,%7},{%8,%9},{%0,%1,%2,%3};"
                 : "+f"(c[0]), "+f"(c[1]), "+f"(c[2]), "+f"(c[3])
                 : "r"(a[0]), "r"(a[1]), "r"(a[2]), "r"(a[3]), "r"(b0), "r"(b1));
}
__device__ __forceinline__ void ldfrag(const uint32_t* hb, int w0, int r0, int r1,
                                       uint32_t* ah, uint32_t* al) {
    ah[0] = hb[r0 * 128 + w0];             ah[1] = hb[r1 * 128 + w0];
    ah[2] = hb[r0 * 128 + w0 + 4];         ah[3] = hb[r1 * 128 + w0 + 4];
    al[0] = hb[16384 + r0 * 128 + w0];     al[1] = hb[16384 + r1 * 128 + w0];
    al[2] = hb[16384 + r0 * 128 + w0 + 4]; al[3] = hb[16384 + r1 * 128 + w0 + 4];
}

// ---------------------------------------------------------------------------
__global__ void prep(const int* __restrict__ cam, const float* __restrict__ Wi,
                     const float* __restrict__ Wh, const float* __restrict__ Wc) {
    if (blockIdx.x == 0) {
        __shared__ int cn[Cc], cu[Cc], co[Cc];
        int tid = threadIdx.x;
        if (tid < Cc) cn[tid] = 0;
        if (tid < MAXG) g_bar[tid] = 0;
        __syncthreads();
        for (int b = tid; b < Bn; b += blockDim.x) atomicAdd(&cn[cam[b]], 1);
        __syncthreads();
        if (tid == 0) {
            int o = 0;
            for (int c = 0; c < Cc; c++) { co[c] = o; cu[c] = o; o += cn[c]; }
            int g = 0;
            for (int c = 0; c < Cc; c++)
                for (int s = 0; s < cn[c] && g < MAXG; s += 128) {
                    g_gcam[g] = c; g_goff[g] = co[c] + s; g_gcnt[g] = min(128, cn[c] - s); g++;
                }
            g_ngrp = g;
        }
        __syncthreads();
        for (int b = tid; b < Bn; b += blockDim.x) { int p = atomicAdd(&cu[cam[b]], 1); g_perm[p] = b; }
    }
    int idx = blockIdx.x * blockDim.x + threadIdx.x, st = gridDim.x * blockDim.x;
    const int NWG = 240 * 6 * 512;
    for (int i = idx; i < NWG; i += st) {
        int lane = i & 31, kc = (i >> 5) & 15, T = (i >> 9) % 6, tile = i / (512 * 6);
        int c = tile >> 4, j = tile & 15;
        size_t row = (size_t)c * Gn + (T >> 1) * 256 + 16 * j + 8 * (T & 1) + (lane >> 2);
        int k0 = 16 * kc + (lane & 3) * 2;
        size_t o = (size_t)tile * 3072 + (T * 16 + kc) * 32 + lane;
        uint32_t h0, l0, h1, l1;
        const float* w = Wh + row * Hn;
        bfsplit2(w[k0], w[k0 + 1], h0, l0); bfsplit2(w[k0 + 8], w[k0 + 9], h1, l1);
        g_Bw[o] = make_uint4(h0, h1, l0, l1);
        w = Wi + row * Hn;
        bfsplit2(w[k0], w[k0 + 1], h0, l0); bfsplit2(w[k0 + 8], w[k0 + 9], h1, l1);
        g_Bx[o] = make_uint4(h0, h1, l0, l1);
    }
    const int NWO = 240 * 4 * 512;
    for (int i = idx; i < NWO; i += st) {
        int lane = i & 31, kc = (i >> 5) & 15, T = (i >> 9) & 3, tile = i / (512 * 4);
        int c = tile >> 4, j = tile & 15;
        const float* w = Wc + ((size_t)c * On + 32 * j + 8 * T + (lane >> 2)) * Hn;
        int k0 = 16 * kc + (lane & 3) * 2;
        uint32_t h0, l0, h1, l1;
        bfsplit2(w[k0], w[k0 + 1], h0, l0); bfsplit2(w[k0 + 8], w[k0 + 9], h1, l1);
        g_Bo[(size_t)tile * 2048 + (T * 16 + kc) * 32 + lane] = make_uint4(h0, h1, l0, l1);
    }
}

// ---------------------------------------------------------------------------
// 288 CTAs x 256 threads, 2 CTAs/SM (launch_bounds). Warp w owns m-tile
// mt=(w-rot)&7 for BOTH gate (step i) and out (step i-1) GEMMs, fused,
// sharing A-fragments (R13 structure at half N-width).
// ---------------------------------------------------------------------------
__global__ void __launch_bounds__(256, 2)
gru(const float* __restrict__ x, const float* __restrict__ b_ih,
    const float* __restrict__ b_hh, const float* __restrict__ bc,
    float* __restrict__ out) {
    extern __shared__ __align__(16) uint4 sm4[];
    uint4* sB  = sm4;                        // 3072 uint4 (gate)
    uint4* sBo = sm4 + 3072;                 // 2048 uint4 (out)
    float* bcs = (float*)(sm4 + 5120);       // 32
    float* bhs = bcs + 32;                   // 16
    int* samp  = (int*)(bhs + 16);           // 128

    const int grp = blockIdx.x >> 4, j = blockIdx.x & 15;
    if (grp >= g_ngrp) return;
    const int cam = g_gcam[grp], off0 = g_goff[grp], cnt = g_gcnt[grp];
    const int tile = cam * NS + j;
    const int tid = threadIdx.x, wid = tid >> 5, lane = tid & 31;
    const int qr = lane >> 2, qc = lane & 3;
    const int na = (cnt + 15) >> 4;
    const int rot = (grp + j) & 7;
    const int mt = (wid - rot) & 7;
    const bool act = mt < na;
    const int r0 = 16 * mt + qr, r1 = r0 + 8;

    if (tid < 128) samp[tid] = (tid < cnt) ? g_perm[off0 + tid] : 0;
    if (tid < 32) bcs[tid] = bc[cam * On + 32 * j + tid];
    if (tid < 16) bhs[tid] = b_hh[cam * Gn + 512 + 16 * j + tid];
    {
        const uint4* s = g_Bw + (size_t)tile * 3072;
        for (int i = tid; i < 3072; i += 256) sB[i] = s[i];
        const uint4* s2 = g_Bo + (size_t)tile * 2048;
        for (int i = tid; i < 2048; i += 256) sBo[i] = s2[i];
    }
    __syncthreads();

    float gi[24], hold[8];
    if (act) {  // gi = x@Wi + biases
#pragma unroll
        for (int q = 0; q < 24; q++) gi[q] = 0.f;
        const uint4* bx = g_Bx + (size_t)tile * 3072;
        const float* x0 = (r0 < cnt) ? x + (size_t)samp[r0] * Hn : 0;
        const float* x1 = (r1 < cnt) ? x + (size_t)samp[r1] * Hn : 0;
        for (int kc = 0; kc < 16; kc++) {
            int k0 = 16 * kc + qc * 2;
            float2 p00 = x0 ? *(const float2*)(x0 + k0) : make_float2(0.f, 0.f);
            float2 p02 = x0 ? *(const float2*)(x0 + k0 + 8) : make_float2(0.f, 0.f);
            float2 p10 = x1 ? *(const float2*)(x1 + k0) : make_float2(0.f, 0.f);
            float2 p12 = x1 ? *(const float2*)(x1 + k0 + 8) : make_float2(0.f, 0.f);
            uint32_t ah[4], al[4];
            bfsplit2(p00.x, p00.y, ah[0], al[0]);
            bfsplit2(p10.x, p10.y, ah[1], al[1]);
            bfsplit2(p02.x, p02.y, ah[2], al[2]);
            bfsplit2(p12.x, p12.y, ah[3], al[3]);
            uint4 bg[6];
#pragma unroll
            for (int T = 0; T < 6; T++) bg[T] = bx[(T * 16 + kc) * 32 + lane];
#pragma unroll
            for (int T = 0; T < 6; T++) mma4(gi + 4 * T, ah, bg[T].x, bg[T].y);
#pragma unroll
            for (int T = 0; T < 6; T++) mma4(gi + 4 * T, ah, bg[T].z, bg[T].w);
#pragma unroll
            for (int T = 0; T < 6; T++) mma4(gi + 4 * T, al, bg[T].x, bg[T].y);
        }
#pragma unroll
        for (int T = 0; T < 6; T++) {
            int g = T >> 1;
            int col = g * 256 + 16 * j + 8 * (T & 1) + qc * 2;
            float b0 = b_ih[cam * Gn + col], b1 = b_ih[cam * Gn + col + 1];
            if (g < 2) { b0 += b_hh[cam * Gn + col]; b1 += b_hh[cam * Gn + col + 1]; }
            gi[4 * T] += b0; gi[4 * T + 1] += b1; gi[4 * T + 2] += b0; gi[4 * T + 3] += b1;
        }
    }
#pragma unroll
    for (int q = 0; q < 8; q++) hold[q] = 0.f;
    int bt = 0;

    for (int i = 0; i <= Tn; i++) {
        float gacc[24], oacc[16];
        if (act) {
#pragma unroll
            for (int q = 0; q < 24; q++) gacc[q] = 0.f;
#pragma unroll
            for (int q = 0; q < 16; q++) oacc[q] = 0.f;
            if (i > 0) {
                const uint32_t* hb = g_h + (size_t)((i & 1) * MAXG + grp) * 2 * 16384;
                const bool dog = i < Tn;
                uint32_t ah[4], al[4], nh[4], nl[4];
                ldfrag(hb, qc, r0, r1, ah, al);
                for (int kc = 0; kc < 16; kc++) {
                    if (kc < 15) ldfrag(hb, qc + 8 * (kc + 1), r0, r1, nh, nl);
                    uint4 bo[4];
#pragma unroll
                    for (int T = 0; T < 4; T++) bo[T] = sBo[(T * 16 + kc) * 32 + lane];
                    if (dog) {
                        uint4 bg[6];
#pragma unroll
                        for (int T = 0; T < 6; T++) bg[T] = sB[(T * 16 + kc) * 32 + lane];
#pragma unroll
                        for (int T = 0; T < 6; T++) mma4(gacc + 4 * T, ah, bg[T].x, bg[T].y);
#pragma unroll
                        for (int T = 0; T < 4; T++) mma4(oacc + 4 * T, ah, bo[T].x, bo[T].y);
#pragma unroll
                        for (int T = 0; T < 6; T++) mma4(gacc + 4 * T, ah, bg[T].z, bg[T].w);
#pragma unroll
                        for (int T = 0; T < 4; T++) mma4(oacc + 4 * T, ah, bo[T].z, bo[T].w);
#pragma unroll
                        for (int T = 0; T < 6; T++) mma4(gacc + 4 * T, al, bg[T].x, bg[T].y);
#pragma unroll
                        for (int T = 0; T < 4; T++) mma4(oacc + 4 * T, al, bo[T].x, bo[T].y);
                    } else {
#pragma unroll
                        for (int T = 0; T < 4; T++) mma4(oacc + 4 * T, ah, bo[T].x, bo[T].y);
#pragma unroll
                        for (int T = 0; T < 4; T++) mma4(oacc + 4 * T, ah, bo[T].z, bo[T].w);
#pragma unroll
                        for (int T = 0; T < 4; T++) mma4(oacc + 4 * T, al, bo[T].x, bo[T].y);
                    }
#pragma unroll
                    for (int q = 0; q < 4; q++) { ah[q] = nh[q]; al[q] = nl[q]; }
                }
            }
            if (i < Tn) {  // gate epilogue -> h_{i+1} (16 cols of slice j)
                uint32_t* dh = g_h + (size_t)(((i + 1) & 1) * MAXG + grp) * 2 * 16384;
#pragma unroll
                for (int h = 0; h < 2; h++) {
                    const int Tr = h, Tz = 2 + h, Tk = 4 + h;
                    int cb = 8 * h + qc * 2;
                    float bn0 = bhs[cb], bn1 = bhs[cb + 1];
                    float h00, h01, h10, h11;
                    { float r = sigf(gi[Tr * 4] + gacc[Tr * 4]);
                      float z = sigf(gi[Tz * 4] + gacc[Tz * 4]);
                      float n = tanhf_(gi[Tk * 4] + r * (gacc[Tk * 4] + bn0));
                      h00 = (1.f - z) * n + z * hold[4 * h]; hold[4 * h] = h00; }
                    { float r = sigf(gi[Tr * 4 + 1] + gacc[Tr * 4 + 1]);
                      float z = sigf(gi[Tz * 4 + 1] + gacc[Tz * 4 + 1]);
                      float n = tanhf_(gi[Tk * 4 + 1] + r * (gacc[Tk * 4 + 1] + bn1));
                      h01 = (1.f - z) * n + z * hold[4 * h + 1]; hold[4 * h + 1] = h01; }
                    { float r = sigf(gi[Tr * 4 + 2] + gacc[Tr * 4 + 2]);
                      float z = sigf(gi[Tz * 4 + 2] + gacc[Tz * 4 + 2]);
                      float n = tanhf_(gi[Tk * 4 + 2] + r * (gacc[Tk * 4 + 2] + bn0));
                      h10 = (1.f - z) * n + z * hold[4 * h + 2]; hold[4 * h + 2] = h10; }
                    { float r = sigf(gi[Tr * 4 + 3] + gacc[Tr * 4 + 3]);
                      float z = sigf(gi[Tz * 4 + 3] + gacc[Tz * 4 + 3]);
                      float n = tanhf_(gi[Tk * 4 + 3] + r * (gacc[Tk * 4 + 3] + bn1));
                      h11 = (1.f - z) * n + z * hold[4 * h + 3]; hold[4 * h + 3] = h11; }
                    uint32_t w0h, w0l, w1h, w1l;
                    bfsplit2(h00, h01, w0h, w0l);
                    bfsplit2(h10, h11, w1h, w1l);
                    int wrd = 8 * j + 4 * h + qc;
                    dh[r0 * 128 + wrd] = w0h; dh[r1 * 128 + wrd] = w1h;
                    dh[16384 + r0 * 128 + wrd] = w0l; dh[16384 + r1 * 128 + wrd] = w1l;
                }
            }
            if (i > 0) {  // out epilogue: t = i-1 (32 cols of slice j)
#pragma unroll
                for (int T = 0; T < 4; T++) {
                    int cl = 8 * T + qc * 2, col = 32 * j + cl;
                    float b0 = bcs[cl], b1 = bcs[cl + 1];
                    if (r0 < cnt) {
                        float* p = out + (size_t)samp[r0] * OT + (size_t)col * Tn + (i - 1);
                        p[0] = sigf(oacc[4 * T] + b0); p[Tn] = sigf(oacc[4 * T + 1] + b1);
                    }
                    if (r1 < cnt) {
                        float* p = out + (size_t)samp[r1] * OT + (size_t)col * Tn + (i - 1);
                        p[0] = sigf(oacc[4 * T + 2] + b0); p[Tn] = sigf(oacc[4 * T + 3] + b1);
                    }
                }
            }
        }
        if (i < Tn) {   // per-group barrier (16 CTAs, all resident)
            __threadfence();
            __syncthreads();
            bt += NS;
            if (tid == 0) {
                atomicAdd(&g_bar[grp], 1);
                int v;
                do {
                    asm volatile("ld.global.acquire.gpu.b32 %0,[%1];" : "=r"(v) : "l"(&g_bar[grp]) : "memory");
                } while (v < bt);
            }
            __syncthreads();
        }
    }
}

// ---------------------------------------------------------------------------
extern "C" void kernel_launch(void* const* d_in, const int* in_sizes, int n_in,
                              void* d_out, int out_size) {
    const float* x    = (const float*)d_in[0];
    const int*   cam  = (const int*)  d_in[1];
    const float* W_ih = (const float*)d_in[2];
    const float* W_hh = (const float*)d_in[3];
    const float* b_ih = (const float*)d_in[4];
    const float* b_hh = (const float*)d_in[5];
    const float* Wc   = (const float*)d_in[6];
    const float* bc   = (const float*)d_in[7];
    float* out = (float*)d_out;
    // 5120 uint4 (81920) + 32f + 16f + 128i (704) = 82624 -> pad 82688
    const int smem = 82688;
    cudaFuncSetAttribute(gru, cudaFuncAttributeMaxDynamicSharedMemorySize, smem);
    prep<<<1024, 256>>>(cam, W_ih, W_hh, Wc);
    gru<<<MAXG * NS, 256, smem>>>(x, b_ih, b_hh, bc, out);
}